// round 4
// baseline (speedup 1.0000x reference)
#include <cuda_runtime.h>
#include <math.h>

#define BB 2
#define SS 2048
#define DDIM 1024
#define HH 16
#define DH 64

// Scratch (no allocation allowed): Qh/Kh/Vh in [B,H,S,64], ctx in [B,S,D]
__device__ float g_qh[BB*SS*DDIM];
__device__ float g_kh[BB*SS*DDIM];
__device__ float g_vh[BB*SS*DDIM];
__device__ float g_ctx[BB*SS*DDIM];

// ---------------------------------------------------------------------------
// SGEMM: C = A[M,K] @ W[K,N] + bias[N]
// BM=BN=128, BK=8, 256 threads, 8x8 per thread.
// SPLIT==1: write C in head-split layout [B,H,S,64] (m=b*S+s, n=h*64+d)
// ---------------------------------------------------------------------------
template<int SPLIT>
__global__ void __launch_bounds__(256)
gemm_kernel(const float* __restrict__ A, const float* __restrict__ W,
            const float* __restrict__ bias, float* __restrict__ C,
            int M, int N, int K)
{
    __shared__ float As[8][128];
    __shared__ float Ws[8][128];

    const int tid = threadIdx.x;
    const int tx = tid & 15;        // n dim
    const int ty = tid >> 4;        // m dim
    const int m0 = blockIdx.y * 128;
    const int n0 = blockIdx.x * 128;

    float acc[8][8];
    #pragma unroll
    for (int i = 0; i < 8; i++)
        #pragma unroll
        for (int j = 0; j < 8; j++) acc[i][j] = 0.f;

    const int arow = tid >> 1;      // 0..127
    const int aseg = (tid & 1) * 4; // 0 or 4
    const int wrow = tid >> 5;      // 0..7
    const int wcol = (tid & 31) * 4;

    const float* Aptr = A + (size_t)(m0 + arow) * K + aseg;
    const float* Wptr = W + (size_t)wrow * N + n0 + wcol;

    for (int k0 = 0; k0 < K; k0 += 8) {
        float4 av = *(const float4*)(Aptr + k0);
        float4 wv = *(const float4*)(Wptr + (size_t)k0 * N);
        As[aseg + 0][arow] = av.x;
        As[aseg + 1][arow] = av.y;
        As[aseg + 2][arow] = av.z;
        As[aseg + 3][arow] = av.w;
        *(float4*)&Ws[wrow][wcol] = wv;
        __syncthreads();

        #pragma unroll
        for (int kk = 0; kk < 8; kk++) {
            float4 a0 = *(float4*)&As[kk][ty * 8];
            float4 a1 = *(float4*)&As[kk][ty * 8 + 4];
            float4 b0 = *(float4*)&Ws[kk][tx * 8];
            float4 b1 = *(float4*)&Ws[kk][tx * 8 + 4];
            float a[8] = {a0.x, a0.y, a0.z, a0.w, a1.x, a1.y, a1.z, a1.w};
            float b[8] = {b0.x, b0.y, b0.z, b0.w, b1.x, b1.y, b1.z, b1.w};
            #pragma unroll
            for (int i = 0; i < 8; i++)
                #pragma unroll
                for (int j = 0; j < 8; j++)
                    acc[i][j] += a[i] * b[j];
        }
        __syncthreads();
    }

    // epilogue
    #pragma unroll
    for (int i = 0; i < 8; i++) {
        int m = m0 + ty * 8 + i;
        #pragma unroll
        for (int j = 0; j < 8; j++) {
            int n = n0 + tx * 8 + j;
            float v = acc[i][j] + bias[n];
            if (SPLIT) {
                int b = m / SS;
                int s = m - b * SS;
                int h = n >> 6;
                int d = n & 63;
                C[(((size_t)(b * HH + h)) * SS + s) * DH + d] = v;
            } else {
                C[(size_t)m * N + n] = v;
            }
        }
    }
}

// ---------------------------------------------------------------------------
// Fused flash attention (fp32). One block = one (b, h, 64-query tile).
// 256 threads as 16x16; 4x4 micro-tiles for both score and PV GEMMs.
// Smem: Qt[64][64] (d-major), KV[64][64] (K: d-major, then V: k-major),
//       St[64][65] scores k-major (pad 65 -> conflict-free column access),
//       red[64][4], rm/rl/ral[64].
// ---------------------------------------------------------------------------
#define ATT_SMEM ((64*64 + 64*64 + 64*65 + 64*4 + 64*3) * 4)

__global__ void __launch_bounds__(256)
attn_kernel(const float* __restrict__ Q, const float* __restrict__ K,
            const float* __restrict__ V, float* __restrict__ O)
{
    extern __shared__ float sm[];
    float* Qt  = sm;                 // 4096
    float* KV  = Qt + 64 * 64;       // 4096
    float* St  = KV + 64 * 64;       // 64*65
    float* red = St + 64 * 65;       // 256
    float* rm  = red + 256;          // 64
    float* rl  = rm + 64;            // 64
    float* ral = rl + 64;            // 64

    const int tid = threadIdx.x;
    const int tx = tid & 15;   // k / d dim
    const int ty = tid >> 4;   // q dim
    const int b = blockIdx.z, h = blockIdx.y;
    const int q0 = blockIdx.x * 64;
    const float scale = 0.125f;  // 1/sqrt(64)

    const size_t base = ((size_t)(b * HH + h)) * SS * DH;
    const float* Qp = Q + base + (size_t)q0 * DH;

    // Load Q tile transposed (d-major), pre-scaled
    #pragma unroll
    for (int r = 0; r < 4; r++) {
        int e = tid + r * 256;       // 0..1023 float4s
        int srow = e >> 4;           // 0..63
        int dseg = (e & 15) * 4;     // 0..60
        float4 v = *(const float4*)(Qp + srow * 64 + dseg);
        Qt[(dseg + 0) * 64 + srow] = v.x * scale;
        Qt[(dseg + 1) * 64 + srow] = v.y * scale;
        Qt[(dseg + 2) * 64 + srow] = v.z * scale;
        Qt[(dseg + 3) * 64 + srow] = v.w * scale;
    }
    if (tid < 64) { rm[tid] = -INFINITY; rl[tid] = 0.f; }

    float oacc[4][4];  // [q][d]
    #pragma unroll
    for (int i = 0; i < 4; i++)
        #pragma unroll
        for (int j = 0; j < 4; j++) oacc[i][j] = 0.f;

    __syncthreads();

    const int qrow = tid >> 2;   // 0..63 (softmax ownership)
    const int pseg = tid & 3;    // 0..3

    for (int k0 = 0; k0 < SS; k0 += 64) {
        // ---- load K tile transposed (d-major) ----
        const float* Kp = K + base + (size_t)k0 * DH;
        #pragma unroll
        for (int r = 0; r < 4; r++) {
            int e = tid + r * 256;
            int srow = e >> 4;
            int dseg = (e & 15) * 4;
            float4 v = *(const float4*)(Kp + srow * 64 + dseg);
            KV[(dseg + 0) * 64 + srow] = v.x;
            KV[(dseg + 1) * 64 + srow] = v.y;
            KV[(dseg + 2) * 64 + srow] = v.z;
            KV[(dseg + 3) * 64 + srow] = v.w;
        }
        __syncthreads();

        // ---- scores: S[k][q] = sum_d K[k][d] * Qscaled[q][d] ----
        float sacc[4][4];  // [k][q]
        #pragma unroll
        for (int i = 0; i < 4; i++)
            #pragma unroll
            for (int j = 0; j < 4; j++) sacc[i][j] = 0.f;

        #pragma unroll 8
        for (int d = 0; d < 64; d++) {
            float4 aq = *(float4*)(Qt + d * 64 + ty * 4);
            float4 bk = *(float4*)(KV + d * 64 + tx * 4);
            float aa[4] = {aq.x, aq.y, aq.z, aq.w};
            float bb[4] = {bk.x, bk.y, bk.z, bk.w};
            #pragma unroll
            for (int ki = 0; ki < 4; ki++)
                #pragma unroll
                for (int qj = 0; qj < 4; qj++)
                    sacc[ki][qj] += bb[ki] * aa[qj];
        }
        #pragma unroll
        for (int ki = 0; ki < 4; ki++)
            #pragma unroll
            for (int qj = 0; qj < 4; qj++)
                St[(tx * 4 + ki) * 65 + ty * 4 + qj] = sacc[ki][qj];
        __syncthreads();

        // ---- softmax: partial max (4 threads per q row) ----
        float pm = -INFINITY;
        #pragma unroll
        for (int i = 0; i < 16; i++)
            pm = fmaxf(pm, St[(pseg * 16 + i) * 65 + qrow]);
        red[qrow * 4 + pseg] = pm;
        __syncthreads();

        if (tid < 64) {
            float mo = rm[tid];
            float mn = fmaxf(fmaxf(red[tid * 4 + 0], red[tid * 4 + 1]),
                             fmaxf(red[tid * 4 + 2], red[tid * 4 + 3]));
            mn = fmaxf(mo, mn);
            ral[tid] = __expf(mo - mn);
            rm[tid] = mn;
        }
        __syncthreads();

        // ---- exp + partial row sums ----
        {
            float mv = rm[qrow];
            float psum = 0.f;
            #pragma unroll
            for (int i = 0; i < 16; i++) {
                int idx = (pseg * 16 + i) * 65 + qrow;
                float p = __expf(St[idx] - mv);
                St[idx] = p;
                psum += p;
            }
            red[qrow * 4 + pseg] = psum;
        }
        __syncthreads();

        if (tid < 64) {
            rl[tid] = rl[tid] * ral[tid] +
                      red[tid * 4 + 0] + red[tid * 4 + 1] +
                      red[tid * 4 + 2] + red[tid * 4 + 3];
        }

        // ---- load V tile (k-major) into KV; rescale oacc by alpha ----
        {
            const float4* Vp = (const float4*)(V + base + (size_t)k0 * DH);
            float4* KV4 = (float4*)KV;
            #pragma unroll
            for (int r = 0; r < 4; r++) {
                int e = tid + r * 256;
                KV4[e] = Vp[e];
            }
        }
        #pragma unroll
        for (int qj = 0; qj < 4; qj++) {
            float a = ral[ty * 4 + qj];
            #pragma unroll
            for (int di = 0; di < 4; di++) oacc[qj][di] *= a;
        }
        __syncthreads();

        // ---- O += P @ V ----
        #pragma unroll 8
        for (int j = 0; j < 64; j++) {
            float4 vv = *(float4*)(KV + j * 64 + tx * 4);
            float vb[4] = {vv.x, vv.y, vv.z, vv.w};
            float p0 = St[j * 65 + ty * 4 + 0];
            float p1 = St[j * 65 + ty * 4 + 1];
            float p2 = St[j * 65 + ty * 4 + 2];
            float p3 = St[j * 65 + ty * 4 + 3];
            #pragma unroll
            for (int di = 0; di < 4; di++) {
                oacc[0][di] += p0 * vb[di];
                oacc[1][di] += p1 * vb[di];
                oacc[2][di] += p2 * vb[di];
                oacc[3][di] += p3 * vb[di];
            }
        }
        __syncthreads();
    }

    // ---- epilogue: normalize, write to ctx in [B,S,D] layout ----
    float* Op = O + ((size_t)b * SS + q0) * DDIM + h * DH;
    #pragma unroll
    for (int qj = 0; qj < 4; qj++) {
        int q = ty * 4 + qj;
        float invl = 1.f / rl[q];
        float4 v;
        v.x = oacc[qj][0] * invl;
        v.y = oacc[qj][1] * invl;
        v.z = oacc[qj][2] * invl;
        v.w = oacc[qj][3] * invl;
        *(float4*)(Op + (size_t)q * DDIM + tx * 4) = v;
    }
}

// ---------------------------------------------------------------------------
extern "C" void kernel_launch(void* const* d_in, const int* in_sizes, int n_in,
                              void* d_out, int out_size)
{
    const float* q  = (const float*)d_in[0];
    const float* k  = (const float*)d_in[1];
    const float* v  = (const float*)d_in[2];
    const float* wq = (const float*)d_in[3];
    const float* bq = (const float*)d_in[4];
    const float* wk = (const float*)d_in[5];
    const float* bk = (const float*)d_in[6];
    const float* wv = (const float*)d_in[7];
    const float* bv = (const float*)d_in[8];
    const float* wo = (const float*)d_in[9];
    const float* bo = (const float*)d_in[10];
    float* out = (float*)d_out;

    float *qh, *kh, *vh, *ctx;
    cudaGetSymbolAddress((void**)&qh,  g_qh);
    cudaGetSymbolAddress((void**)&kh,  g_kh);
    cudaGetSymbolAddress((void**)&vh,  g_vh);
    cudaGetSymbolAddress((void**)&ctx, g_ctx);

    const int M = BB * SS;   // 4096
    dim3 gemm_grid(DDIM / 128, M / 128);  // (8, 32)

    gemm_kernel<1><<<gemm_grid, 256>>>(q, wq, bq, qh, M, DDIM, DDIM);
    gemm_kernel<1><<<gemm_grid, 256>>>(k, wk, bk, kh, M, DDIM, DDIM);
    gemm_kernel<1><<<gemm_grid, 256>>>(v, wv, bv, vh, M, DDIM, DDIM);

    cudaFuncSetAttribute(attn_kernel,
                         cudaFuncAttributeMaxDynamicSharedMemorySize, ATT_SMEM);
    attn_kernel<<<dim3(SS / 64, HH, BB), 256, ATT_SMEM>>>(qh, kh, vh, ctx);

    gemm_kernel<0><<<gemm_grid, 256>>>(ctx, wo, bo, out, M, DDIM, DDIM);
}

// round 5
// speedup vs baseline: 1.0019x; 1.0019x over previous
#include <cuda_runtime.h>
#include <math.h>

#define BB 2
#define SS 2048
#define DDIM 1024
#define HH 16
#define DH 64

// Scratch (no allocation allowed): Qh/Kh/Vh in [B,H,S,64], ctx in [B,S,D]
__device__ float g_qh[BB*SS*DDIM];
__device__ float g_kh[BB*SS*DDIM];
__device__ float g_vh[BB*SS*DDIM];
__device__ float g_ctx[BB*SS*DDIM];

// ---------------------------------------------------------------------------
// SGEMM: C = A[M,K] @ W[K,N] + bias[N]
// BM=BN=128, BK=8, 256 threads, 8x8 per thread.
// SPLIT==1: write C in head-split layout [B,H,S,64] (m=b*S+s, n=h*64+d)
// ---------------------------------------------------------------------------
template<int SPLIT>
__global__ void __launch_bounds__(256)
gemm_kernel(const float* __restrict__ A, const float* __restrict__ W,
            const float* __restrict__ bias, float* __restrict__ C,
            int M, int N, int K)
{
    __shared__ float As[8][128];
    __shared__ float Ws[8][128];

    const int tid = threadIdx.x;
    const int tx = tid & 15;        // n dim
    const int ty = tid >> 4;        // m dim
    const int m0 = blockIdx.y * 128;
    const int n0 = blockIdx.x * 128;

    float acc[8][8];
    #pragma unroll
    for (int i = 0; i < 8; i++)
        #pragma unroll
        for (int j = 0; j < 8; j++) acc[i][j] = 0.f;

    const int arow = tid >> 1;      // 0..127
    const int aseg = (tid & 1) * 4; // 0 or 4
    const int wrow = tid >> 5;      // 0..7
    const int wcol = (tid & 31) * 4;

    const float* Aptr = A + (size_t)(m0 + arow) * K + aseg;
    const float* Wptr = W + (size_t)wrow * N + n0 + wcol;

    for (int k0 = 0; k0 < K; k0 += 8) {
        float4 av = *(const float4*)(Aptr + k0);
        float4 wv = *(const float4*)(Wptr + (size_t)k0 * N);
        As[aseg + 0][arow] = av.x;
        As[aseg + 1][arow] = av.y;
        As[aseg + 2][arow] = av.z;
        As[aseg + 3][arow] = av.w;
        *(float4*)&Ws[wrow][wcol] = wv;
        __syncthreads();

        #pragma unroll
        for (int kk = 0; kk < 8; kk++) {
            float4 a0 = *(float4*)&As[kk][ty * 8];
            float4 a1 = *(float4*)&As[kk][ty * 8 + 4];
            float4 b0 = *(float4*)&Ws[kk][tx * 8];
            float4 b1 = *(float4*)&Ws[kk][tx * 8 + 4];
            float a[8] = {a0.x, a0.y, a0.z, a0.w, a1.x, a1.y, a1.z, a1.w};
            float b[8] = {b0.x, b0.y, b0.z, b0.w, b1.x, b1.y, b1.z, b1.w};
            #pragma unroll
            for (int i = 0; i < 8; i++)
                #pragma unroll
                for (int j = 0; j < 8; j++)
                    acc[i][j] += a[i] * b[j];
        }
        __syncthreads();
    }

    // epilogue
    #pragma unroll
    for (int i = 0; i < 8; i++) {
        int m = m0 + ty * 8 + i;
        #pragma unroll
        for (int j = 0; j < 8; j++) {
            int n = n0 + tx * 8 + j;
            float v = acc[i][j] + bias[n];
            if (SPLIT) {
                int b = m / SS;
                int s = m - b * SS;
                int h = n >> 6;
                int d = n & 63;
                C[(((size_t)(b * HH + h)) * SS + s) * DH + d] = v;
            } else {
                C[(size_t)m * N + n] = v;
            }
        }
    }
}

// ---------------------------------------------------------------------------
// Fused flash attention (fp32). One block = one (b, h, 64-query tile).
// 256 threads as 16x16; 4x4 micro-tiles for both score and PV GEMMs.
// Smem: Qt[64][64] (d-major), KV[64][64] (K: d-major, then V: k-major),
//       St[64][65] scores k-major (pad 65 -> conflict-free column access),
//       red[64][4], rm/rl/ral[64].
// ---------------------------------------------------------------------------
#define ATT_SMEM ((64*64 + 64*64 + 64*65 + 64*4 + 64*3) * 4)

__global__ void __launch_bounds__(256)
attn_kernel(const float* __restrict__ Q, const float* __restrict__ K,
            const float* __restrict__ V, float* __restrict__ O)
{
    extern __shared__ float sm[];
    float* Qt  = sm;                 // 4096
    float* KV  = Qt + 64 * 64;       // 4096
    float* St  = KV + 64 * 64;       // 64*65
    float* red = St + 64 * 65;       // 256
    float* rm  = red + 256;          // 64
    float* rl  = rm + 64;            // 64
    float* ral = rl + 64;            // 64

    const int tid = threadIdx.x;
    const int tx = tid & 15;   // k / d dim
    const int ty = tid >> 4;   // q dim
    const int b = blockIdx.z, h = blockIdx.y;
    const int q0 = blockIdx.x * 64;
    const float scale = 0.125f;  // 1/sqrt(64)

    const size_t base = ((size_t)(b * HH + h)) * SS * DH;
    const float* Qp = Q + base + (size_t)q0 * DH;

    // Load Q tile transposed (d-major), pre-scaled
    #pragma unroll
    for (int r = 0; r < 4; r++) {
        int e = tid + r * 256;       // 0..1023 float4s
        int srow = e >> 4;           // 0..63
        int dseg = (e & 15) * 4;     // 0..60
        float4 v = *(const float4*)(Qp + srow * 64 + dseg);
        Qt[(dseg + 0) * 64 + srow] = v.x * scale;
        Qt[(dseg + 1) * 64 + srow] = v.y * scale;
        Qt[(dseg + 2) * 64 + srow] = v.z * scale;
        Qt[(dseg + 3) * 64 + srow] = v.w * scale;
    }
    if (tid < 64) { rm[tid] = -INFINITY; rl[tid] = 0.f; }

    float oacc[4][4];  // [q][d]
    #pragma unroll
    for (int i = 0; i < 4; i++)
        #pragma unroll
        for (int j = 0; j < 4; j++) oacc[i][j] = 0.f;

    __syncthreads();

    const int qrow = tid >> 2;   // 0..63 (softmax ownership)
    const int pseg = tid & 3;    // 0..3

    for (int k0 = 0; k0 < SS; k0 += 64) {
        // ---- load K tile transposed (d-major) ----
        const float* Kp = K + base + (size_t)k0 * DH;
        #pragma unroll
        for (int r = 0; r < 4; r++) {
            int e = tid + r * 256;
            int srow = e >> 4;
            int dseg = (e & 15) * 4;
            float4 v = *(const float4*)(Kp + srow * 64 + dseg);
            KV[(dseg + 0) * 64 + srow] = v.x;
            KV[(dseg + 1) * 64 + srow] = v.y;
            KV[(dseg + 2) * 64 + srow] = v.z;
            KV[(dseg + 3) * 64 + srow] = v.w;
        }
        __syncthreads();

        // ---- scores: S[k][q] = sum_d K[k][d] * Qscaled[q][d] ----
        float sacc[4][4];  // [k][q]
        #pragma unroll
        for (int i = 0; i < 4; i++)
            #pragma unroll
            for (int j = 0; j < 4; j++) sacc[i][j] = 0.f;

        #pragma unroll 8
        for (int d = 0; d < 64; d++) {
            float4 aq = *(float4*)(Qt + d * 64 + ty * 4);
            float4 bk = *(float4*)(KV + d * 64 + tx * 4);
            float aa[4] = {aq.x, aq.y, aq.z, aq.w};
            float bb[4] = {bk.x, bk.y, bk.z, bk.w};
            #pragma unroll
            for (int ki = 0; ki < 4; ki++)
                #pragma unroll
                for (int qj = 0; qj < 4; qj++)
                    sacc[ki][qj] += bb[ki] * aa[qj];
        }
        #pragma unroll
        for (int ki = 0; ki < 4; ki++)
            #pragma unroll
            for (int qj = 0; qj < 4; qj++)
                St[(tx * 4 + ki) * 65 + ty * 4 + qj] = sacc[ki][qj];
        __syncthreads();

        // ---- softmax: partial max (4 threads per q row) ----
        float pm = -INFINITY;
        #pragma unroll
        for (int i = 0; i < 16; i++)
            pm = fmaxf(pm, St[(pseg * 16 + i) * 65 + qrow]);
        red[qrow * 4 + pseg] = pm;
        __syncthreads();

        if (tid < 64) {
            float mo = rm[tid];
            float mn = fmaxf(fmaxf(red[tid * 4 + 0], red[tid * 4 + 1]),
                             fmaxf(red[tid * 4 + 2], red[tid * 4 + 3]));
            mn = fmaxf(mo, mn);
            ral[tid] = __expf(mo - mn);
            rm[tid] = mn;
        }
        __syncthreads();

        // ---- exp + partial row sums ----
        {
            float mv = rm[qrow];
            float psum = 0.f;
            #pragma unroll
            for (int i = 0; i < 16; i++) {
                int idx = (pseg * 16 + i) * 65 + qrow;
                float p = __expf(St[idx] - mv);
                St[idx] = p;
                psum += p;
            }
            red[qrow * 4 + pseg] = psum;
        }
        __syncthreads();

        if (tid < 64) {
            rl[tid] = rl[tid] * ral[tid] +
                      red[tid * 4 + 0] + red[tid * 4 + 1] +
                      red[tid * 4 + 2] + red[tid * 4 + 3];
        }

        // ---- load V tile (k-major) into KV; rescale oacc by alpha ----
        {
            const float4* Vp = (const float4*)(V + base + (size_t)k0 * DH);
            float4* KV4 = (float4*)KV;
            #pragma unroll
            for (int r = 0; r < 4; r++) {
                int e = tid + r * 256;
                KV4[e] = Vp[e];
            }
        }
        #pragma unroll
        for (int qj = 0; qj < 4; qj++) {
            float a = ral[ty * 4 + qj];
            #pragma unroll
            for (int di = 0; di < 4; di++) oacc[qj][di] *= a;
        }
        __syncthreads();

        // ---- O += P @ V ----
        #pragma unroll 8
        for (int j = 0; j < 64; j++) {
            float4 vv = *(float4*)(KV + j * 64 + tx * 4);
            float vb[4] = {vv.x, vv.y, vv.z, vv.w};
            float p0 = St[j * 65 + ty * 4 + 0];
            float p1 = St[j * 65 + ty * 4 + 1];
            float p2 = St[j * 65 + ty * 4 + 2];
            float p3 = St[j * 65 + ty * 4 + 3];
            #pragma unroll
            for (int di = 0; di < 4; di++) {
                oacc[0][di] += p0 * vb[di];
                oacc[1][di] += p1 * vb[di];
                oacc[2][di] += p2 * vb[di];
                oacc[3][di] += p3 * vb[di];
            }
        }
        __syncthreads();
    }

    // ---- epilogue: normalize, write to ctx in [B,S,D] layout ----
    float* Op = O + ((size_t)b * SS + q0) * DDIM + h * DH;
    #pragma unroll
    for (int qj = 0; qj < 4; qj++) {
        int q = ty * 4 + qj;
        float invl = 1.f / rl[q];
        float4 v;
        v.x = oacc[qj][0] * invl;
        v.y = oacc[qj][1] * invl;
        v.z = oacc[qj][2] * invl;
        v.w = oacc[qj][3] * invl;
        *(float4*)(Op + (size_t)q * DDIM + tx * 4) = v;
    }
}

// ---------------------------------------------------------------------------
extern "C" void kernel_launch(void* const* d_in, const int* in_sizes, int n_in,
                              void* d_out, int out_size)
{
    const float* q  = (const float*)d_in[0];
    const float* k  = (const float*)d_in[1];
    const float* v  = (const float*)d_in[2];
    const float* wq = (const float*)d_in[3];
    const float* bq = (const float*)d_in[4];
    const float* wk = (const float*)d_in[5];
    const float* bk = (const float*)d_in[6];
    const float* wv = (const float*)d_in[7];
    const float* bv = (const float*)d_in[8];
    const float* wo = (const float*)d_in[9];
    const float* bo = (const float*)d_in[10];
    float* out = (float*)d_out;

    float *qh, *kh, *vh, *ctx;
    cudaGetSymbolAddress((void**)&qh,  g_qh);
    cudaGetSymbolAddress((void**)&kh,  g_kh);
    cudaGetSymbolAddress((void**)&vh,  g_vh);
    cudaGetSymbolAddress((void**)&ctx, g_ctx);

    const int M = BB * SS;   // 4096
    dim3 gemm_grid(DDIM / 128, M / 128);  // (8, 32)

    gemm_kernel<1><<<gemm_grid, 256>>>(q, wq, bq, qh, M, DDIM, DDIM);
    gemm_kernel<1><<<gemm_grid, 256>>>(k, wk, bk, kh, M, DDIM, DDIM);
    gemm_kernel<1><<<gemm_grid, 256>>>(v, wv, bv, vh, M, DDIM, DDIM);

    cudaFuncSetAttribute(attn_kernel,
                         cudaFuncAttributeMaxDynamicSharedMemorySize, ATT_SMEM);
    attn_kernel<<<dim3(SS / 64, HH, BB), 256, ATT_SMEM>>>(qh, kh, vh, ctx);

    gemm_kernel<0><<<gemm_grid, 256>>>(ctx, wo, bo, out, M, DDIM, DDIM);
}